// round 2
// baseline (speedup 1.0000x reference)
#include <cuda_runtime.h>
#include <cuda_bf16.h>

// ---------------- scratch (static device memory only; no allocation) ----------------
__device__ float g_A1[64 * 4899];        // branch-a pooled features
__device__ float g_h1[64 * 1000];
__device__ float g_h2[64 * 500];
__device__ float g_a3[64 * 9];
__device__ float g_yb[64 * 2 * 4900];    // branch-b stage-1 output
__device__ float g_cat[64 * 15506];      // concat buffer
__device__ float g_z1[64 * 8000];
__device__ float g_z2[64 * 2000];
__device__ float g_part[16 * 64 * 8000]; // split-K partials (32.8 MB)

// ---------------- branch a front: conv3x3(pad1) + relu + maxpool(2,2)s(1,1) ----------
__global__ void k_a_front(const float* __restrict__ x1, const float* __restrict__ w1,
                          const float* __restrict__ b1) {
    int idx = blockIdx.x * blockDim.x + threadIdx.x;
    if (idx >= 64 * 4899) return;
    int b = idx / 4899, j = idx % 4899;
    const float* X = x1 + b * 9800;
    float r0[4], r1[4];
#pragma unroll
    for (int d = 0; d < 4; d++) {
        int c = j - 1 + d;
        bool ok = (c >= 0 && c < 4900);
        r0[d] = ok ? __ldg(&X[c]) : 0.f;
        r1[d] = ok ? __ldg(&X[4900 + c]) : 0.f;
    }
    float W[9];
#pragma unroll
    for (int i = 0; i < 9; i++) W[i] = __ldg(&w1[i]);
    float bb = __ldg(&b1[0]);
    float m = -1e30f;
#pragma unroll
    for (int o = 0; o < 2; o++) {
        // conv at h=0 (x rows 0,1 with w1 rows 1,2)
        float c0 = bb + W[3]*r0[o] + W[4]*r0[o+1] + W[5]*r0[o+2]
                      + W[6]*r1[o] + W[7]*r1[o+1] + W[8]*r1[o+2];
        // conv at h=1 (x rows 0,1 with w1 rows 0,1)
        float c1 = bb + W[0]*r0[o] + W[1]*r0[o+1] + W[2]*r0[o+2]
                      + W[3]*r1[o] + W[4]*r1[o+1] + W[5]*r1[o+2];
        m = fmaxf(m, fmaxf(c0, c1));
    }
    g_A1[idx] = fmaxf(m, 0.f);
}

// ---------------- generic split-K GEMM: C_part = A(64xK) * W(KxN) ---------------------
#define KT 16
#define AS_STRIDE 68

__global__ __launch_bounds__(256, 2)
void k_gemm(const float* __restrict__ A, const float* __restrict__ W,
            float* __restrict__ part, int K, int N, int kSplit) {
    __shared__ float As[KT * AS_STRIDE];
    __shared__ float Ws[KT * 256];
    int n0 = blockIdx.x * 256;
    int ks = blockIdx.y;
    int kLen = (K + kSplit - 1) / kSplit;
    int kbeg = ks * kLen;
    int kend = min(K, kbeg + kLen);
    int t = threadIdx.x;
    int mg = t >> 5, nt = t & 31;
    int m0 = mg * 8;
    unsigned long long acc[4][8];
#pragma unroll
    for (int p = 0; p < 4; p++)
#pragma unroll
        for (int i = 0; i < 8; i++) acc[p][i] = 0ULL;

    int am = t >> 2;
    int aq = (t & 3) * 4;

    for (int k0 = kbeg; k0 < kend; k0 += KT) {
        // A tile -> shared (transposed, [k][m])
#pragma unroll
        for (int i = 0; i < 4; i++) {
            int kg = k0 + aq + i;
            As[(aq + i) * AS_STRIDE + am] = (kg < kend) ? A[am * K + kg] : 0.f;
        }
        // W tile -> shared ([k][n])
#pragma unroll
        for (int r = 0; r < 4; r++) {
            int lin = t + 256 * r;
            int kk = lin >> 6;
            int n4 = (lin & 63) << 2;
            int kg = k0 + kk;
            int ng = n0 + n4;
            float4 v = make_float4(0.f, 0.f, 0.f, 0.f);
            if (kg < kend) {
                if (ng + 3 < N) {
                    v = *reinterpret_cast<const float4*>(&W[kg * N + ng]);
                } else {
                    if (ng + 0 < N) v.x = W[kg * N + ng + 0];
                    if (ng + 1 < N) v.y = W[kg * N + ng + 1];
                    if (ng + 2 < N) v.z = W[kg * N + ng + 2];
                    if (ng + 3 < N) v.w = W[kg * N + ng + 3];
                }
            }
            *reinterpret_cast<float4*>(&Ws[kk * 256 + n4]) = v;
        }
        __syncthreads();
#pragma unroll
        for (int kk = 0; kk < KT; kk++) {
            ulonglong2 a01 = *reinterpret_cast<const ulonglong2*>(&As[kk * AS_STRIDE + m0]);
            ulonglong2 a23 = *reinterpret_cast<const ulonglong2*>(&As[kk * AS_STRIDE + m0 + 4]);
            unsigned long long av[4] = {a01.x, a01.y, a23.x, a23.y};
            float4 w03 = *reinterpret_cast<const float4*>(&Ws[kk * 256 + nt * 4]);
            float4 w47 = *reinterpret_cast<const float4*>(&Ws[kk * 256 + 128 + nt * 4]);
            float wv[8] = {w03.x, w03.y, w03.z, w03.w, w47.x, w47.y, w47.z, w47.w};
#pragma unroll
            for (int i = 0; i < 8; i++) {
                unsigned long long ww;
                unsigned int wu = __float_as_uint(wv[i]);
                asm("mov.b64 %0, {%1,%1};" : "=l"(ww) : "r"(wu));
#pragma unroll
                for (int p = 0; p < 4; p++) {
                    asm("fma.rn.f32x2 %0, %1, %2, %0;"
                        : "+l"(acc[p][i]) : "l"(av[p]), "l"(ww));
                }
            }
        }
        __syncthreads();
    }
    float* out = part + (size_t)ks * 64 * N;
#pragma unroll
    for (int i = 0; i < 8; i++) {
        int ng = n0 + ((i < 4) ? nt * 4 + i : 128 + nt * 4 + (i - 4));
        if (ng < N) {
#pragma unroll
            for (int p = 0; p < 4; p++) {
                unsigned int lo, hi;
                asm("mov.b64 {%0,%1}, %2;" : "=r"(lo), "=r"(hi) : "l"(acc[p][i]));
                out[(m0 + 2 * p) * N + ng]     = __uint_as_float(lo);
                out[(m0 + 2 * p + 1) * N + ng] = __uint_as_float(hi);
            }
        }
    }
}

// ---------------- split-K reduce + bias (+relu) ----------------------------------------
__global__ void k_reduce(const float* __restrict__ bias, float* __restrict__ C,
                         int N, int S, int doRelu) {
    int idx = blockIdx.x * blockDim.x + threadIdx.x;
    if (idx >= 64 * N) return;
    float s = bias[idx % N];
    const float* p = g_part + idx;
    long stride = (long)64 * N;
    for (int j = 0; j < S; j++) s += p[j * stride];
    C[idx] = doRelu ? fmaxf(s, 0.f) : s;
}

// ---------------- tiny GEMM: h2(64x500) @ Wc(500x9) + bc -> a3 -------------------------
__global__ void k_gemm3(const float* __restrict__ Wc, const float* __restrict__ bc) {
    int b = blockIdx.x / 9, n = blockIdx.x % 9;
    int lane = threadIdx.x;
    float s = 0.f;
    for (int k = lane; k < 500; k += 32) s += g_h2[b * 500 + k] * Wc[k * 9 + n];
#pragma unroll
    for (int o = 16; o; o >>= 1) s += __shfl_xor_sync(0xffffffff, s, o);
    if (lane == 0) g_a3[b * 9 + n] = s + bc[n];
}

// ---------------- dynamic per-sample conv + relu + pool(2,2)s(2,2) -> cat[:, :2450] ----
__global__ void k_dyn(const float* __restrict__ x1, const float* __restrict__ lw,
                      const float* __restrict__ lb) {
    __shared__ float sdw[9];
    __shared__ float slb;
    int b = blockIdx.x;
    int tid = threadIdx.x;
    if (tid < 9) sdw[tid] = lw[b * 9 + tid] * g_a3[b * 9 + tid];
    if (tid == 9) slb = lb[b];
    __syncthreads();
    int t = blockIdx.y * blockDim.x + tid;
    if (t >= 2450) return;
    const float* X = x1 + b * 9800;
    float r0[4], r1[4];
    int base = 2 * t - 1;
#pragma unroll
    for (int d = 0; d < 4; d++) {
        int c = base + d;
        bool ok = (c >= 0 && c < 4900);
        r0[d] = ok ? X[c] : 0.f;
        r1[d] = ok ? X[4900 + c] : 0.f;
    }
    float m = -1e30f;
#pragma unroll
    for (int o = 0; o < 2; o++) {
        float c0 = slb + sdw[3]*r0[o] + sdw[4]*r0[o+1] + sdw[5]*r0[o+2]
                       + sdw[6]*r1[o] + sdw[7]*r1[o+1] + sdw[8]*r1[o+2];
        float c1 = slb + sdw[0]*r0[o] + sdw[1]*r0[o+1] + sdw[2]*r0[o+2]
                       + sdw[3]*r1[o] + sdw[4]*r1[o+1] + sdw[5]*r1[o+2];
        m = fmaxf(m, fmaxf(c0, c1));
    }
    g_cat[b * 15506 + t] = fmaxf(m, 0.f);
}

// ---------------- branch b stage 1: conv2x2(pad1)+relu+pool(2,2)s(1,1) -> yb -----------
__global__ void k_b1(const float* __restrict__ x2, const float* __restrict__ w5,
                     const float* __restrict__ b5) {
    int idx = blockIdx.x * blockDim.x + threadIdx.x;
    if (idx >= 64 * 4900) return;
    int b = idx / 4900, w = idx % 4900;
    const float* X = x2 + b * 9800;
    float x0[3], x1v[3];
#pragma unroll
    for (int d = 0; d < 3; d++) {
        int c = w - 1 + d;
        bool ok = (c >= 0 && c < 4900);
        x0[d]  = ok ? X[c] : 0.f;
        x1v[d] = ok ? X[4900 + c] : 0.f;
    }
    float W00 = __ldg(&w5[0]), W01 = __ldg(&w5[1]), W10 = __ldg(&w5[2]), W11 = __ldg(&w5[3]);
    float bb = __ldg(&b5[0]);
    float c0a = bb + W10*x0[0] + W11*x0[1];
    float c0b = bb + W10*x0[1] + W11*x0[2];
    float c1a = bb + W00*x0[0] + W01*x0[1] + W10*x1v[0] + W11*x1v[1];
    float c1b = bb + W00*x0[1] + W01*x0[2] + W10*x1v[1] + W11*x1v[2];
    float c2a = bb + W00*x1v[0] + W01*x1v[1];
    float c2b = bb + W00*x1v[1] + W01*x1v[2];
    float y0 = fmaxf(fmaxf(c0a, c0b), fmaxf(c1a, c1b));
    float y1 = fmaxf(fmaxf(c1a, c1b), fmaxf(c2a, c2b));
    g_yb[b * 9800 + w]        = fmaxf(y0, 0.f);
    g_yb[b * 9800 + 4900 + w] = fmaxf(y1, 0.f);
}

// ---------------- branch b stage 2: conv(32,2x2,s2)+relu+pool(1,6)s6 -> cat[:,2450:] ----
__global__ void k_b2(const float* __restrict__ w6, const float* __restrict__ b6) {
    __shared__ float sy[2][96];
    __shared__ float sw[128];
    __shared__ float sb[32];
    int b = blockIdx.x;
    int u0 = blockIdx.y * 8;
    int tid = threadIdx.y * 32 + threadIdx.x;
    int c0 = u0 * 12;
    if (tid < 192) {
        int row = tid / 96, cc = tid % 96;
        sy[row][cc] = g_yb[b * 9800 + row * 4900 + c0 + cc];
    }
    if (tid < 128) sw[tid] = w6[tid];
    if (tid < 32)  sb[tid] = b6[tid];
    __syncthreads();
    int c = threadIdx.x, ul = threadIdx.y;
    int base = ul * 12;
    float w00 = sw[c*4], w01 = sw[c*4+1], w10 = sw[c*4+2], w11 = sw[c*4+3];
    float best = -1e30f;
#pragma unroll
    for (int r = 0; r < 6; r++) {
        float v = sb[c] + sy[0][base+2*r]*w00 + sy[0][base+2*r+1]*w01
                        + sy[1][base+2*r]*w10 + sy[1][base+2*r+1]*w11;
        best = fmaxf(best, v);
    }
    g_cat[b * 15506 + 2450 + c * 408 + (u0 + ul)] = fmaxf(best, 0.f);
}

// ---------------- final tiny GEMM: z2(64x2000) @ Wf3(2000x2) + bf3 -> out --------------
__global__ void k_f3(const float* __restrict__ Wf3, const float* __restrict__ bf3,
                     float* __restrict__ out) {
    int b = blockIdx.x >> 1, n = blockIdx.x & 1;
    int lane = threadIdx.x;
    float s = 0.f;
    for (int k = lane; k < 2000; k += 32) s += g_z2[b * 2000 + k] * Wf3[k * 2 + n];
#pragma unroll
    for (int o = 16; o; o >>= 1) s += __shfl_xor_sync(0xffffffff, s, o);
    if (lane == 0) out[b * 2 + n] = s + bf3[n];
}

// ---------------- launch ----------------------------------------------------------------
extern "C" void kernel_launch(void* const* d_in, const int* in_sizes, int n_in,
                              void* d_out, int out_size) {
    const float* x1  = (const float*)d_in[0];
    const float* x2  = (const float*)d_in[1];
    const float* w1  = (const float*)d_in[2];
    const float* b1  = (const float*)d_in[3];
    const float* Wa  = (const float*)d_in[4];
    const float* ba  = (const float*)d_in[5];
    const float* Wb  = (const float*)d_in[6];
    const float* bb  = (const float*)d_in[7];
    const float* Wc  = (const float*)d_in[8];
    const float* bc  = (const float*)d_in[9];
    const float* lw  = (const float*)d_in[10];
    const float* lb  = (const float*)d_in[11];
    const float* w5  = (const float*)d_in[12];
    const float* b5  = (const float*)d_in[13];
    const float* w6  = (const float*)d_in[14];
    const float* b6  = (const float*)d_in[15];
    const float* Wf1 = (const float*)d_in[16];
    const float* bf1 = (const float*)d_in[17];
    const float* Wf2 = (const float*)d_in[18];
    const float* bf2 = (const float*)d_in[19];
    const float* Wf3 = (const float*)d_in[20];
    const float* bf3 = (const float*)d_in[21];
    float* out = (float*)d_out;

    float *A1, *h1, *h2, *cat, *z1, *z2, *part;
    cudaGetSymbolAddress((void**)&A1,  g_A1);
    cudaGetSymbolAddress((void**)&h1,  g_h1);
    cudaGetSymbolAddress((void**)&h2,  g_h2);
    cudaGetSymbolAddress((void**)&cat, g_cat);
    cudaGetSymbolAddress((void**)&z1,  g_z1);
    cudaGetSymbolAddress((void**)&z2,  g_z2);
    cudaGetSymbolAddress((void**)&part, g_part);

    // branch a front
    k_a_front<<<(64 * 4899 + 255) / 256, 256>>>(x1, w1, b1);
    // h1 = relu(A1 @ Wa + ba)
    k_gemm<<<dim3(4, 32), 256>>>(A1, Wa, part, 4899, 1000, 32);
    k_reduce<<<(64 * 1000 + 255) / 256, 256>>>(ba, h1, 1000, 32, 1);
    // h2 = relu(h1 @ Wb + bb)
    k_gemm<<<dim3(2, 32), 256>>>(h1, Wb, part, 1000, 500, 32);
    k_reduce<<<(64 * 500 + 255) / 256, 256>>>(bb, h2, 500, 32, 1);
    // a3 = h2 @ Wc + bc
    k_gemm3<<<576, 32>>>(Wc, bc);
    // dynamic conv -> cat[:, :2450]
    k_dyn<<<dim3(64, 10), 256>>>(x1, lw, lb);
    // branch b
    k_b1<<<(64 * 4900 + 255) / 256, 256>>>(x2, w5, b5);
    k_b2<<<dim3(64, 51), dim3(32, 8)>>>(w6, b6);
    // z1 = relu(cat @ Wf1 + bf1)
    k_gemm<<<dim3(32, 16), 256>>>(cat, Wf1, part, 15506, 8000, 16);
    k_reduce<<<(64 * 8000 + 255) / 256, 256>>>(bf1, z1, 8000, 16, 1);
    // z2 = relu(z1 @ Wf2 + bf2)
    k_gemm<<<dim3(8, 32), 256>>>(z1, Wf2, part, 8000, 2000, 32);
    k_reduce<<<(64 * 2000 + 255) / 256, 256>>>(bf2, z2, 2000, 32, 1);
    // out = z2 @ Wf3 + bf3
    k_f3<<<128, 32>>>(Wf3, bf3, out);
}

// round 4
// speedup vs baseline: 1.3964x; 1.3964x over previous
#include <cuda_runtime.h>
#include <cuda_bf16.h>
#include <cstdint>

// ============================ scratch =========================================
#define CAT_LDA 15520
__device__ float g_A1[64 * 4900];
__device__ float g_h1[64 * 1000];
__device__ float g_h2[64 * 500];
__device__ float g_a3[64 * 9];
__device__ float g_yb[64 * 2 * 4900];
__device__ float g_cat[64 * CAT_LDA];
__device__ float g_z1[64 * 8000];
__device__ float g_z2[64 * 2000];
__device__ float g_part[2 * 1024 * 1024];

// ============================ bf16 mma.sync split-K GEMM ======================
// part[ks][b][n] = sum_{k in split} A[b][k] * W[k][n]
// 3-term bf16 split: Ah*Bh + Al*Bh + Ah*Bl, fp32 accumulate.
#define ASTRIDE 20            // uint32 words per A row (16 kp + 4 pad)
#define BSTRIDE 136           // uint32 words per B kp-row (128 n + 8 pad)
#define A_TERM_WORDS (64 * ASTRIDE)   // 1280
#define B_TERM_WORDS (16 * BSTRIDE)   // 2176
#define STAGE_WORDS (2 * A_TERM_WORDS + 2 * B_TERM_WORDS)  // 6912 words = 27648 B
#define SMEM_MMA_BYTES (2 * STAGE_WORDS * 4)               // 55296 B

__device__ __forceinline__ uint32_t pk_bf16(__nv_bfloat16 a, __nv_bfloat16 b) {
    return (uint32_t)__bfloat16_as_ushort(a) | ((uint32_t)__bfloat16_as_ushort(b) << 16);
}

__device__ __forceinline__ void mma_bf16(float* d, uint32_t a0, uint32_t a1,
                                         uint32_t a2, uint32_t a3,
                                         uint32_t b0, uint32_t b1) {
    asm volatile(
        "mma.sync.aligned.m16n8k16.row.col.f32.bf16.bf16.f32 "
        "{%0,%1,%2,%3}, {%4,%5,%6,%7}, {%8,%9}, {%0,%1,%2,%3};"
        : "+f"(d[0]), "+f"(d[1]), "+f"(d[2]), "+f"(d[3])
        : "r"(a0), "r"(a1), "r"(a2), "r"(a3), "r"(b0), "r"(b1));
}

__global__ __launch_bounds__(256, 2)
void k_mma(const float* __restrict__ A, int lda,
           const float* __restrict__ W,
           float* __restrict__ part,
           int K, int N, int kLen)
{
    extern __shared__ uint32_t sm[];
    int t = threadIdx.x;
    int n0 = blockIdx.x * 128;
    int ks = blockIdx.y;
    int kbeg = ks * kLen;
    int kend = min(K, kbeg + kLen);
    int C = (kend - kbeg + 31) >> 5;

    int w = t >> 5, l = t & 31;
    int wm = (w & 3) * 16;        // warp row base
    int wn = (w >> 2) * 64;       // warp col base

    float acc[8][4];
#pragma unroll
    for (int j = 0; j < 8; j++)
#pragma unroll
        for (int e = 0; e < 4; e++) acc[j][e] = 0.f;

    // gload/sts assignments
    int am   = t >> 2;            // A row 0..63
    int akp  = t & 3;             // A kp base (+4i)
    int bn   = t & 127;           // B n within tile
    int bkp0 = (t >> 7) * 8;      // B kp base (0 or 8)
    bool bn_ok = (n0 + bn) < N;

    float aV[8];
    float bV[16];

    // ---- prologue: load + convert + store chunk 0 ----
    {
        int k0 = kbeg;
#pragma unroll
        for (int i = 0; i < 4; i++) {
            int k = k0 + 2 * (akp + 4 * i);
            aV[2*i]   = (k     < kend) ? A[(size_t)am * lda + k]     : 0.f;
            aV[2*i+1] = (k + 1 < kend) ? A[(size_t)am * lda + k + 1] : 0.f;
        }
#pragma unroll
        for (int j = 0; j < 8; j++) {
            int k = k0 + 2 * (bkp0 + j);
            bV[2*j]   = (bn_ok && k     < kend) ? W[(size_t)k * N + n0 + bn]       : 0.f;
            bV[2*j+1] = (bn_ok && k + 1 < kend) ? W[(size_t)(k + 1) * N + n0 + bn] : 0.f;
        }
    }

    for (int c = 0; c < C; c++) {
        // store current chunk's converted data into stage c&1
        {
            uint32_t* S = sm + (c & 1) * STAGE_WORDS;
#pragma unroll
            for (int i = 0; i < 4; i++) {
                int kp = akp + 4 * i;
                float v0 = aV[2*i], v1 = aV[2*i+1];
                __nv_bfloat16 h0 = __float2bfloat16(v0), h1 = __float2bfloat16(v1);
                float r0 = v0 - __bfloat162float(h0), r1 = v1 - __bfloat162float(h1);
                S[am * ASTRIDE + kp] = pk_bf16(h0, h1);
                S[A_TERM_WORDS + am * ASTRIDE + kp] =
                    pk_bf16(__float2bfloat16(r0), __float2bfloat16(r1));
            }
#pragma unroll
            for (int j = 0; j < 8; j++) {
                int kp = bkp0 + j;
                float v0 = bV[2*j], v1 = bV[2*j+1];
                __nv_bfloat16 h0 = __float2bfloat16(v0), h1 = __float2bfloat16(v1);
                float r0 = v0 - __bfloat162float(h0), r1 = v1 - __bfloat162float(h1);
                S[2 * A_TERM_WORDS + kp * BSTRIDE + bn] = pk_bf16(h0, h1);
                S[2 * A_TERM_WORDS + B_TERM_WORDS + kp * BSTRIDE + bn] =
                    pk_bf16(__float2bfloat16(r0), __float2bfloat16(r1));
            }
        }
        __syncthreads();

        // issue global loads for next chunk while computing this one
        if (c + 1 < C) {
            int k0 = kbeg + 32 * (c + 1);
#pragma unroll
            for (int i = 0; i < 4; i++) {
                int k = k0 + 2 * (akp + 4 * i);
                aV[2*i]   = (k     < kend) ? A[(size_t)am * lda + k]     : 0.f;
                aV[2*i+1] = (k + 1 < kend) ? A[(size_t)am * lda + k + 1] : 0.f;
            }
#pragma unroll
            for (int j = 0; j < 8; j++) {
                int k = k0 + 2 * (bkp0 + j);
                bV[2*j]   = (bn_ok && k     < kend) ? W[(size_t)k * N + n0 + bn]       : 0.f;
                bV[2*j+1] = (bn_ok && k + 1 < kend) ? W[(size_t)(k + 1) * N + n0 + bn] : 0.f;
            }
        }

        // compute chunk c from stage c&1
        {
            const uint32_t* S  = sm + (c & 1) * STAGE_WORDS;
            const uint32_t* Ah = S;
            const uint32_t* Al = S + A_TERM_WORDS;
            const uint32_t* Bh = S + 2 * A_TERM_WORDS;
            const uint32_t* Bl = S + 2 * A_TERM_WORDS + B_TERM_WORDS;
            int r  = wm + (l >> 2);
            int kq = l & 3;
#pragma unroll
            for (int h = 0; h < 2; h++) {
                int kpA = kq + 8 * h;
                uint32_t ah0 = Ah[r * ASTRIDE + kpA];
                uint32_t ah1 = Ah[(r + 8) * ASTRIDE + kpA];
                uint32_t ah2 = Ah[r * ASTRIDE + kpA + 4];
                uint32_t ah3 = Ah[(r + 8) * ASTRIDE + kpA + 4];
                uint32_t al0 = Al[r * ASTRIDE + kpA];
                uint32_t al1 = Al[(r + 8) * ASTRIDE + kpA];
                uint32_t al2 = Al[r * ASTRIDE + kpA + 4];
                uint32_t al3 = Al[(r + 8) * ASTRIDE + kpA + 4];
#pragma unroll
                for (int j = 0; j < 8; j++) {
                    int n = wn + j * 8 + (l >> 2);
                    uint32_t bh0 = Bh[kpA * BSTRIDE + n];
                    uint32_t bh1 = Bh[(kpA + 4) * BSTRIDE + n];
                    uint32_t bl0 = Bl[kpA * BSTRIDE + n];
                    uint32_t bl1 = Bl[(kpA + 4) * BSTRIDE + n];
                    mma_bf16(acc[j], ah0, ah1, ah2, ah3, bh0, bh1);
                    mma_bf16(acc[j], al0, al1, al2, al3, bh0, bh1);
                    mma_bf16(acc[j], ah0, ah1, ah2, ah3, bl0, bl1);
                }
            }
        }
        if (c + 1 < C) __syncthreads();
    }

    // ---- epilogue: write split-K partials ----
    float* o = part + (size_t)ks * 64 * N;
    int r = wm + (l >> 2);
#pragma unroll
    for (int j = 0; j < 8; j++) {
        int n = wn + j * 8 + (l & 3) * 2;
        if (n0 + n < N) {   // N always even, n even -> pair safe
            *(float2*)&o[(size_t)r * N + n0 + n]       = make_float2(acc[j][0], acc[j][1]);
            *(float2*)&o[(size_t)(r + 8) * N + n0 + n] = make_float2(acc[j][2], acc[j][3]);
        }
    }
}

// ---------------- split-K reduce + bias + relu --------------------------------
__global__ void k_reduce(const float* __restrict__ bias, float* __restrict__ C,
                         int N, int S, int doRelu) {
    int idx = blockIdx.x * blockDim.x + threadIdx.x;
    if (idx >= 64 * N) return;
    float s = bias[idx % N];
    const float* p = g_part + idx;
    long stride = (long)64 * N;
    for (int j = 0; j < S; j++) s += p[j * stride];
    C[idx] = doRelu ? fmaxf(s, 0.f) : s;
}

// ---------------- branch a front: conv3x3(pad1)+relu+pool(2,2)s(1,1) ----------
__global__ void k_a_front(const float* __restrict__ x1, const float* __restrict__ w1,
                          const float* __restrict__ b1) {
    int idx = blockIdx.x * blockDim.x + threadIdx.x;
    if (idx >= 64 * 4899) return;
    int b = idx / 4899, j = idx % 4899;
    const float* X = x1 + b * 9800;
    float r0[4], r1[4];
#pragma unroll
    for (int d = 0; d < 4; d++) {
        int c = j - 1 + d;
        bool ok = (c >= 0 && c < 4900);
        r0[d] = ok ? __ldg(&X[c]) : 0.f;
        r1[d] = ok ? __ldg(&X[4900 + c]) : 0.f;
    }
    float W[9];
#pragma unroll
    for (int i = 0; i < 9; i++) W[i] = __ldg(&w1[i]);
    float bb = __ldg(&b1[0]);
    float m = -1e30f;
#pragma unroll
    for (int o = 0; o < 2; o++) {
        float c0 = bb + W[3]*r0[o] + W[4]*r0[o+1] + W[5]*r0[o+2]
                      + W[6]*r1[o] + W[7]*r1[o+1] + W[8]*r1[o+2];
        float c1 = bb + W[0]*r0[o] + W[1]*r0[o+1] + W[2]*r0[o+2]
                      + W[3]*r1[o] + W[4]*r1[o+1] + W[5]*r1[o+2];
        m = fmaxf(m, fmaxf(c0, c1));
    }
    g_A1[b * 4900 + j] = fmaxf(m, 0.f);
}

// ---------------- tiny GEMM: h2 @ Wc + bc -> a3 --------------------------------
__global__ void k_gemm3(const float* __restrict__ Wc, const float* __restrict__ bc) {
    int b = blockIdx.x / 9, n = blockIdx.x % 9;
    int lane = threadIdx.x;
    float s = 0.f;
    for (int k = lane; k < 500; k += 32) s += g_h2[b * 500 + k] * Wc[k * 9 + n];
#pragma unroll
    for (int o = 16; o; o >>= 1) s += __shfl_xor_sync(0xffffffff, s, o);
    if (lane == 0) g_a3[b * 9 + n] = s + bc[n];
}

// ---------------- dynamic conv + relu + pool(2,2)s2 -> cat[:, :2450] -----------
__global__ void k_dyn(const float* __restrict__ x1, const float* __restrict__ lw,
                      const float* __restrict__ lb) {
    __shared__ float sdw[9];
    __shared__ float slb;
    int b = blockIdx.x;
    int tid = threadIdx.x;
    if (tid < 9) sdw[tid] = lw[b * 9 + tid] * g_a3[b * 9 + tid];
    if (tid == 9) slb = lb[b];
    __syncthreads();
    int t = blockIdx.y * blockDim.x + tid;
    if (t >= 2450) return;
    const float* X = x1 + b * 9800;
    float r0[4], r1[4];
    int base = 2 * t - 1;
#pragma unroll
    for (int d = 0; d < 4; d++) {
        int c = base + d;
        bool ok = (c >= 0 && c < 4900);
        r0[d] = ok ? X[c] : 0.f;
        r1[d] = ok ? X[4900 + c] : 0.f;
    }
    float m = -1e30f;
#pragma unroll
    for (int o = 0; o < 2; o++) {
        float c0 = slb + sdw[3]*r0[o] + sdw[4]*r0[o+1] + sdw[5]*r0[o+2]
                       + sdw[6]*r1[o] + sdw[7]*r1[o+1] + sdw[8]*r1[o+2];
        float c1 = slb + sdw[0]*r0[o] + sdw[1]*r0[o+1] + sdw[2]*r0[o+2]
                       + sdw[3]*r1[o] + sdw[4]*r1[o+1] + sdw[5]*r1[o+2];
        m = fmaxf(m, fmaxf(c0, c1));
    }
    g_cat[b * CAT_LDA + t] = fmaxf(m, 0.f);
}

// ---------------- branch b stage 1 ----------------------------------------------
__global__ void k_b1(const float* __restrict__ x2, const float* __restrict__ w5,
                     const float* __restrict__ b5) {
    int idx = blockIdx.x * blockDim.x + threadIdx.x;
    if (idx >= 64 * 4900) return;
    int b = idx / 4900, w = idx % 4900;
    const float* X = x2 + b * 9800;
    float x0[3], x1v[3];
#pragma unroll
    for (int d = 0; d < 3; d++) {
        int c = w - 1 + d;
        bool ok = (c >= 0 && c < 4900);
        x0[d]  = ok ? X[c] : 0.f;
        x1v[d] = ok ? X[4900 + c] : 0.f;
    }
    float W00 = __ldg(&w5[0]), W01 = __ldg(&w5[1]), W10 = __ldg(&w5[2]), W11 = __ldg(&w5[3]);
    float bb = __ldg(&b5[0]);
    float c0a = bb + W10*x0[0] + W11*x0[1];
    float c0b = bb + W10*x0[1] + W11*x0[2];
    float c1a = bb + W00*x0[0] + W01*x0[1] + W10*x1v[0] + W11*x1v[1];
    float c1b = bb + W00*x0[1] + W01*x0[2] + W10*x1v[1] + W11*x1v[2];
    float c2a = bb + W00*x1v[0] + W01*x1v[1];
    float c2b = bb + W00*x1v[1] + W01*x1v[2];
    float y0 = fmaxf(fmaxf(c0a, c0b), fmaxf(c1a, c1b));
    float y1 = fmaxf(fmaxf(c1a, c1b), fmaxf(c2a, c2b));
    g_yb[b * 9800 + w]        = fmaxf(y0, 0.f);
    g_yb[b * 9800 + 4900 + w] = fmaxf(y1, 0.f);
}

// ---------------- branch b stage 2 -> cat[:, 2450:] ------------------------------
__global__ void k_b2(const float* __restrict__ w6, const float* __restrict__ b6) {
    __shared__ float sy[2][96];
    __shared__ float sw[128];
    __shared__ float sb2[32];
    int b = blockIdx.x;
    int u0 = blockIdx.y * 8;
    int tid = threadIdx.y * 32 + threadIdx.x;
    int c0 = u0 * 12;
    if (tid < 192) {
        int row = tid / 96, cc = tid % 96;
        sy[row][cc] = g_yb[b * 9800 + row * 4900 + c0 + cc];
    }
    if (tid < 128) sw[tid] = w6[tid];
    if (tid < 32)  sb2[tid] = b6[tid];
    __syncthreads();
    int c = threadIdx.x, ul = threadIdx.y;
    int base = ul * 12;
    float w00 = sw[c*4], w01 = sw[c*4+1], w10 = sw[c*4+2], w11 = sw[c*4+3];
    float best = -1e30f;
#pragma unroll
    for (int r = 0; r < 6; r++) {
        float v = sb2[c] + sy[0][base+2*r]*w00 + sy[0][base+2*r+1]*w01
                         + sy[1][base+2*r]*w10 + sy[1][base+2*r+1]*w11;
        best = fmaxf(best, v);
    }
    g_cat[b * CAT_LDA + 2450 + c * 408 + (u0 + ul)] = fmaxf(best, 0.f);
}

// ---------------- final tiny GEMM -------------------------------------------------
__global__ void k_f3(const float* __restrict__ Wf3, const float* __restrict__ bf3,
                     float* __restrict__ out) {
    int b = blockIdx.x >> 1, n = blockIdx.x & 1;
    int lane = threadIdx.x;
    float s = 0.f;
    for (int k = lane; k < 2000; k += 32) s += g_z2[b * 2000 + k] * Wf3[k * 2 + n];
#pragma unroll
    for (int o = 16; o; o >>= 1) s += __shfl_xor_sync(0xffffffff, s, o);
    if (lane == 0) out[b * 2 + n] = s + bf3[n];
}

// ---------------- launch -----------------------------------------------------------
extern "C" void kernel_launch(void* const* d_in, const int* in_sizes, int n_in,
                              void* d_out, int out_size) {
    const float* x1  = (const float*)d_in[0];
    const float* x2  = (const float*)d_in[1];
    const float* w1  = (const float*)d_in[2];
    const float* b1  = (const float*)d_in[3];
    const float* Wa  = (const float*)d_in[4];
    const float* ba  = (const float*)d_in[5];
    const float* Wb  = (const float*)d_in[6];
    const float* bb  = (const float*)d_in[7];
    const float* Wc  = (const float*)d_in[8];
    const float* bc  = (const float*)d_in[9];
    const float* lw  = (const float*)d_in[10];
    const float* lb  = (const float*)d_in[11];
    const float* w5  = (const float*)d_in[12];
    const float* b5  = (const float*)d_in[13];
    const float* w6  = (const float*)d_in[14];
    const float* b6  = (const float*)d_in[15];
    const float* Wf1 = (const float*)d_in[16];
    const float* bf1 = (const float*)d_in[17];
    const float* Wf2 = (const float*)d_in[18];
    const float* bf2 = (const float*)d_in[19];
    const float* Wf3 = (const float*)d_in[20];
    const float* bf3 = (const float*)d_in[21];
    float* out = (float*)d_out;

    float *A1, *h1, *h2, *cat, *z1, *z2, *part;
    cudaGetSymbolAddress((void**)&A1,  g_A1);
    cudaGetSymbolAddress((void**)&h1,  g_h1);
    cudaGetSymbolAddress((void**)&h2,  g_h2);
    cudaGetSymbolAddress((void**)&cat, g_cat);
    cudaGetSymbolAddress((void**)&z1,  g_z1);
    cudaGetSymbolAddress((void**)&z2,  g_z2);
    cudaGetSymbolAddress((void**)&part, g_part);

    static int smem_set = 0;
    if (!smem_set) {
        cudaFuncSetAttribute(k_mma, cudaFuncAttributeMaxDynamicSharedMemorySize,
                             SMEM_MMA_BYTES);
        smem_set = 1;
    }

    // branch a front
    k_a_front<<<(64 * 4899 + 255) / 256, 256>>>(x1, w1, b1);
    // h1 = relu(A1 @ Wa + ba): K=4899, N=1000
    k_mma<<<dim3(8, 16), 256, SMEM_MMA_BYTES>>>(A1, 4900, Wa, part, 4899, 1000, 320);
    k_reduce<<<(64 * 1000 + 255) / 256, 256>>>(ba, h1, 1000, 16, 1);
    // h2 = relu(h1 @ Wb + bb): K=1000, N=500
    k_mma<<<dim3(4, 8), 256, SMEM_MMA_BYTES>>>(h1, 1000, Wb, part, 1000, 500, 128);
    k_reduce<<<(64 * 500 + 255) / 256, 256>>>(bb, h2, 500, 8, 1);
    // a3 = h2 @ Wc + bc
    k_gemm3<<<576, 32>>>(Wc, bc);
    // dynamic conv -> cat[:, :2450]
    k_dyn<<<dim3(64, 10), 256>>>(x1, lw, lb);
    // branch b
    k_b1<<<(64 * 4900 + 255) / 256, 256>>>(x2, w5, b5);
    k_b2<<<dim3(64, 51), dim3(32, 8)>>>(w6, b6);
    // z1 = relu(cat @ Wf1 + bf1): K=15506, N=8000
    k_mma<<<dim3(63, 2), 256, SMEM_MMA_BYTES>>>(cat, CAT_LDA, Wf1, part, 15506, 8000, 7753);
    k_reduce<<<(64 * 8000 + 255) / 256, 256>>>(bf1, z1, 8000, 2, 1);
    // z2 = relu(z1 @ Wf2 + bf2): K=8000, N=2000
    k_mma<<<dim3(16, 8), 256, SMEM_MMA_BYTES>>>(z1, 8000, Wf2, part, 8000, 2000, 1000);
    k_reduce<<<(64 * 2000 + 255) / 256, 256>>>(bf2, z2, 2000, 8, 1);
    // out = z2 @ Wf3 + bf3
    k_f3<<<128, 32>>>(Wf3, bf3, out);
}

// round 5
// speedup vs baseline: 2.2188x; 1.5890x over previous
#include <cuda_runtime.h>
#include <cuda_bf16.h>
#include <cstdint>

// ============================ scratch =========================================
#define A1_LDA 5120      // Wa: 32 splits x 160
#define H1_LDA 1024      // Wb: 32 x 32
#define CAT_LDA 15616    // Wf1: 4 x 3904
#define Z1_LDA 8192      // Wf2: 16 x 512
__device__ float g_A1[64 * A1_LDA];
__device__ float g_h1[64 * H1_LDA];
__device__ float g_h2[64 * 500];
__device__ float g_a3[64 * 9];
__device__ float g_yb[64 * 2 * 4900];
__device__ float g_cat[64 * CAT_LDA];
__device__ float g_z1[64 * Z1_LDA];
__device__ float g_z2[64 * 2000];
__device__ float g_part[2 * 1024 * 1024];

// ============================ mma helpers =====================================
__device__ __forceinline__ uint32_t smem_u32(const void* p) {
    uint32_t a;
    asm("{ .reg .u64 t; cvta.to.shared.u64 t, %1; cvt.u32.u64 %0, t; }" : "=r"(a) : "l"(p));
    return a;
}
__device__ __forceinline__ uint32_t pk_bf16(float a, float b) {
    __nv_bfloat162 h = __floats2bfloat162_rn(a, b);
    return *reinterpret_cast<uint32_t*>(&h);
}
__device__ __forceinline__ void ldsm4(uint32_t* r, uint32_t a) {
    asm volatile("ldmatrix.sync.aligned.m8n8.x4.shared.b16 {%0,%1,%2,%3}, [%4];"
                 : "=r"(r[0]), "=r"(r[1]), "=r"(r[2]), "=r"(r[3]) : "r"(a));
}
__device__ __forceinline__ void mma_bf16(float* d, const uint32_t* a,
                                         uint32_t b0, uint32_t b1) {
    asm volatile(
        "mma.sync.aligned.m16n8k16.row.col.f32.bf16.bf16.f32 "
        "{%0,%1,%2,%3}, {%4,%5,%6,%7}, {%8,%9}, {%0,%1,%2,%3};"
        : "+f"(d[0]), "+f"(d[1]), "+f"(d[2]), "+f"(d[3])
        : "r"(a[0]), "r"(a[1]), "r"(a[2]), "r"(a[3]), "r"(b0), "r"(b1));
}

// ============================ bf16 mma split-K GEMM ===========================
// part[ks][b][n] = sum_{k in split} A[b][k] * W[k][n]
// 3-term bf16 split: Ah*Bh + Al*Bh + Ah*Bl, fp32 accumulate.
// SMEM stage layout (words): Ah[0,1280) Al[1280,2560) Bh[2560,5120) Bl[5120,7680)
// A rows: 64 x stride 20 (16 kp + pad). B rows: 128 n x stride 20 (16 kp + pad).
#define STG_WORDS 7680
#define SMEM_MMA_BYTES (2 * STG_WORDS * 4)   // 61440

__global__ __launch_bounds__(256, 2)
void k_mma(const float* __restrict__ A, int lda,
           const float* __restrict__ W,
           float* __restrict__ part,
           int K, int N, int kLen)
{
    extern __shared__ uint32_t sm[];
    const int t = threadIdx.x;
    const int n0 = blockIdx.x * 128;
    const int ks = blockIdx.y;
    const int kbeg = ks * kLen;
    const int kend = min(K, kbeg + kLen);
    const int C = (kend - kbeg + 31) >> 5;

    const int w = t >> 5, l = t & 31;
    const int wm = (w & 1) * 32;
    const int wn = (w >> 1) * 32;

    float acc[2][4][4];
#pragma unroll
    for (int mi = 0; mi < 2; mi++)
#pragma unroll
        for (int nj = 0; nj < 4; nj++)
#pragma unroll
            for (int e = 0; e < 4; e++) acc[mi][nj][e] = 0.f;

    const int am = t >> 2, ak = t & 3;      // A loader: row am, k-slice ak*8
    const int bn = t & 127, kh = t >> 7;    // B loader: col bn, k-half kh*16
    const bool bn_ok = (n0 + bn) < N;

    float aV[8], bV[16];

    // ---- global load of one 32-k chunk into registers (A unguarded via pads) --
    auto gload = [&](int kc) {
        const float* Ap = A + (size_t)am * lda + kc + ak * 8;
        float4 v0 = *(const float4*)Ap;
        float4 v1 = *(const float4*)(Ap + 4);
        aV[0] = v0.x; aV[1] = v0.y; aV[2] = v0.z; aV[3] = v0.w;
        aV[4] = v1.x; aV[5] = v1.y; aV[6] = v1.z; aV[7] = v1.w;
        int kb = kc + kh * 16;
        const float* Wp = W + (size_t)kb * N + n0 + bn;
#pragma unroll
        for (int i = 0; i < 16; i++)
            bV[i] = (bn_ok && (kb + i) < kend) ? Wp[(size_t)i * N] : 0.f;
    };

    // ---- convert + store to shared ------------------------------------------
    auto sts = [&](int buf) {
        uint32_t* S = sm + buf * STG_WORDS;
        uint32_t hw[4], lw[4];
#pragma unroll
        for (int i = 0; i < 4; i++) {
            float v0 = aV[2 * i], v1 = aV[2 * i + 1];
            float h0 = __bfloat162float(__float2bfloat16(v0));
            float h1 = __bfloat162float(__float2bfloat16(v1));
            hw[i] = pk_bf16(h0, h1);
            lw[i] = pk_bf16(v0 - h0, v1 - h1);
        }
        int ai = am * 20 + ak * 4;
        *(uint4*)&S[ai]        = make_uint4(hw[0], hw[1], hw[2], hw[3]);
        *(uint4*)&S[1280 + ai] = make_uint4(lw[0], lw[1], lw[2], lw[3]);
        uint32_t bh[8], bl[8];
#pragma unroll
        for (int j = 0; j < 8; j++) {
            float v0 = bV[2 * j], v1 = bV[2 * j + 1];
            float h0 = __bfloat162float(__float2bfloat16(v0));
            float h1 = __bfloat162float(__float2bfloat16(v1));
            bh[j] = pk_bf16(h0, h1);
            bl[j] = pk_bf16(v0 - h0, v1 - h1);
        }
        int bi = 2560 + bn * 20 + kh * 8;
        *(uint4*)&S[bi]            = make_uint4(bh[0], bh[1], bh[2], bh[3]);
        *(uint4*)&S[bi + 4]        = make_uint4(bh[4], bh[5], bh[6], bh[7]);
        *(uint4*)&S[bi + 2560]     = make_uint4(bl[0], bl[1], bl[2], bl[3]);
        *(uint4*)&S[bi + 2560 + 4] = make_uint4(bl[4], bl[5], bl[6], bl[7]);
    };

    // ---- compute chunk via ldmatrix + mma ------------------------------------
    const uint32_t sb0 = smem_u32(sm);
    const uint32_t arow = (l & 7) + ((l >> 3) & 1) * 8;
    const uint32_t acol = (l >> 4) * 4;
    const uint32_t brow = (l & 7) + (l >> 4) * 8;
    const uint32_t bcol = ((l >> 3) & 1) * 4;
    auto compute = [&](int buf) {
        uint32_t sb = sb0 + buf * (STG_WORDS * 4);
#pragma unroll
        for (int h = 0; h < 2; h++) {
            uint32_t aH[2][4], aL[2][4], bH[2][4], bL[2][4];
#pragma unroll
            for (int mi = 0; mi < 2; mi++) {
                uint32_t ad = sb + ((wm + mi * 16 + arow) * 20 + acol + h * 8) * 4;
                ldsm4(aH[mi], ad);
                ldsm4(aL[mi], ad + 1280 * 4);
            }
#pragma unroll
            for (int nb = 0; nb < 2; nb++) {
                uint32_t bd = sb + ((2560 + (wn + nb * 16 + brow) * 20) + bcol + h * 8) * 4;
                ldsm4(bH[nb], bd);
                ldsm4(bL[nb], bd + 2560 * 4);
            }
#pragma unroll
            for (int mi = 0; mi < 2; mi++)
#pragma unroll
                for (int nj = 0; nj < 4; nj++) {
                    uint32_t b0h = bH[nj >> 1][(nj & 1) * 2], b1h = bH[nj >> 1][(nj & 1) * 2 + 1];
                    uint32_t b0l = bL[nj >> 1][(nj & 1) * 2], b1l = bL[nj >> 1][(nj & 1) * 2 + 1];
                    mma_bf16(acc[mi][nj], aH[mi], b0h, b1h);
                    mma_bf16(acc[mi][nj], aL[mi], b0h, b1h);
                    mma_bf16(acc[mi][nj], aH[mi], b0l, b1l);
                }
        }
    };

    if (C > 0) gload(kbeg);
    for (int c = 0; c < C; c++) {
        sts(c & 1);
        __syncthreads();
        if (c + 1 < C) gload(kbeg + 32 * (c + 1));
        compute(c & 1);
        if (c + 1 < C) __syncthreads();
    }

    // ---- epilogue: split-K partials ------------------------------------------
    float* o = part + (size_t)ks * 64 * N;
#pragma unroll
    for (int mi = 0; mi < 2; mi++)
#pragma unroll
        for (int nj = 0; nj < 4; nj++) {
            int rr = wm + 16 * mi + (l >> 2);
            int n = wn + 8 * nj + (l & 3) * 2;
            if (n0 + n < N) {
                *(float2*)&o[(size_t)rr * N + n0 + n] =
                    make_float2(acc[mi][nj][0], acc[mi][nj][1]);
                *(float2*)&o[(size_t)(rr + 8) * N + n0 + n] =
                    make_float2(acc[mi][nj][2], acc[mi][nj][3]);
            }
        }
}

// ---------------- split-K reduce + bias + relu (ldc-padded output) -------------
__global__ void k_reduce(const float* __restrict__ bias, float* __restrict__ C,
                         int N, int ldc, int S, int doRelu) {
    int idx = blockIdx.x * blockDim.x + threadIdx.x;
    if (idx >= 64 * ldc) return;
    int b = idx / ldc, col = idx % ldc;
    if (col >= N) { C[idx] = 0.f; return; }
    float s = bias[col];
    const float* p = g_part + (size_t)b * N + col;
    long stride = (long)64 * N;
    for (int j = 0; j < S; j++) s += p[j * stride];
    C[idx] = doRelu ? fmaxf(s, 0.f) : s;
}

// ---------------- branch a front: conv3x3(pad1)+relu+pool(2,2)s(1,1) ----------
__global__ void k_a_front(const float* __restrict__ x1, const float* __restrict__ w1,
                          const float* __restrict__ b1) {
    int idx = blockIdx.x * blockDim.x + threadIdx.x;
    if (idx >= 64 * A1_LDA) return;
    int b = idx / A1_LDA, j = idx % A1_LDA;
    if (j >= 4899) { g_A1[idx] = 0.f; return; }
    const float* X = x1 + b * 9800;
    float r0[4], r1[4];
#pragma unroll
    for (int d = 0; d < 4; d++) {
        int c = j - 1 + d;
        bool ok = (c >= 0 && c < 4900);
        r0[d] = ok ? __ldg(&X[c]) : 0.f;
        r1[d] = ok ? __ldg(&X[4900 + c]) : 0.f;
    }
    float W[9];
#pragma unroll
    for (int i = 0; i < 9; i++) W[i] = __ldg(&w1[i]);
    float bb = __ldg(&b1[0]);
    float m = -1e30f;
#pragma unroll
    for (int o = 0; o < 2; o++) {
        float c0 = bb + W[3]*r0[o] + W[4]*r0[o+1] + W[5]*r0[o+2]
                      + W[6]*r1[o] + W[7]*r1[o+1] + W[8]*r1[o+2];
        float c1 = bb + W[0]*r0[o] + W[1]*r0[o+1] + W[2]*r0[o+2]
                      + W[3]*r1[o] + W[4]*r1[o+1] + W[5]*r1[o+2];
        m = fmaxf(m, fmaxf(c0, c1));
    }
    g_A1[idx] = fmaxf(m, 0.f);
}

// ---------------- zero pad columns of cat --------------------------------------
__global__ void k_zcat() {
    int idx = blockIdx.x * blockDim.x + threadIdx.x;
    int b = idx / (CAT_LDA - 15506), j = idx % (CAT_LDA - 15506);
    if (b < 64) g_cat[b * CAT_LDA + 15506 + j] = 0.f;
}

// ---------------- tiny GEMM: h2 @ Wc + bc -> a3 --------------------------------
__global__ void k_gemm3(const float* __restrict__ Wc, const float* __restrict__ bc) {
    int b = blockIdx.x / 9, n = blockIdx.x % 9;
    int lane = threadIdx.x;
    float s = 0.f;
    for (int k = lane; k < 500; k += 32) s += g_h2[b * 500 + k] * Wc[k * 9 + n];
#pragma unroll
    for (int o = 16; o; o >>= 1) s += __shfl_xor_sync(0xffffffff, s, o);
    if (lane == 0) g_a3[b * 9 + n] = s + bc[n];
}

// ---------------- dynamic conv + relu + pool(2,2)s2 -> cat[:, :2450] -----------
__global__ void k_dyn(const float* __restrict__ x1, const float* __restrict__ lw,
                      const float* __restrict__ lb) {
    __shared__ float sdw[9];
    __shared__ float slb;
    int b = blockIdx.x;
    int tid = threadIdx.x;
    if (tid < 9) sdw[tid] = lw[b * 9 + tid] * g_a3[b * 9 + tid];
    if (tid == 9) slb = lb[b];
    __syncthreads();
    int t = blockIdx.y * blockDim.x + tid;
    if (t >= 2450) return;
    const float* X = x1 + b * 9800;
    float r0[4], r1[4];
    int base = 2 * t - 1;
#pragma unroll
    for (int d = 0; d < 4; d++) {
        int c = base + d;
        bool ok = (c >= 0 && c < 4900);
        r0[d] = ok ? X[c] : 0.f;
        r1[d] = ok ? X[4900 + c] : 0.f;
    }
    float m = -1e30f;
#pragma unroll
    for (int o = 0; o < 2; o++) {
        float c0 = slb + sdw[3]*r0[o] + sdw[4]*r0[o+1] + sdw[5]*r0[o+2]
                       + sdw[6]*r1[o] + sdw[7]*r1[o+1] + sdw[8]*r1[o+2];
        float c1 = slb + sdw[0]*r0[o] + sdw[1]*r0[o+1] + sdw[2]*r0[o+2]
                       + sdw[3]*r1[o] + sdw[4]*r1[o+1] + sdw[5]*r1[o+2];
        m = fmaxf(m, fmaxf(c0, c1));
    }
    g_cat[b * CAT_LDA + t] = fmaxf(m, 0.f);
}

// ---------------- branch b stage 1 ----------------------------------------------
__global__ void k_b1(const float* __restrict__ x2, const float* __restrict__ w5,
                     const float* __restrict__ b5) {
    int idx = blockIdx.x * blockDim.x + threadIdx.x;
    if (idx >= 64 * 4900) return;
    int b = idx / 4900, w = idx % 4900;
    const float* X = x2 + b * 9800;
    float x0[3], x1v[3];
#pragma unroll
    for (int d = 0; d < 3; d++) {
        int c = w - 1 + d;
        bool ok = (c >= 0 && c < 4900);
        x0[d]  = ok ? X[c] : 0.f;
        x1v[d] = ok ? X[4900 + c] : 0.f;
    }
    float W00 = __ldg(&w5[0]), W01 = __ldg(&w5[1]), W10 = __ldg(&w5[2]), W11 = __ldg(&w5[3]);
    float bb = __ldg(&b5[0]);
    float c0a = bb + W10*x0[0] + W11*x0[1];
    float c0b = bb + W10*x0[1] + W11*x0[2];
    float c1a = bb + W00*x0[0] + W01*x0[1] + W10*x1v[0] + W11*x1v[1];
    float c1b = bb + W00*x0[1] + W01*x0[2] + W10*x1v[1] + W11*x1v[2];
    float c2a = bb + W00*x1v[0] + W01*x1v[1];
    float c2b = bb + W00*x1v[1] + W01*x1v[2];
    float y0 = fmaxf(fmaxf(c0a, c0b), fmaxf(c1a, c1b));
    float y1 = fmaxf(fmaxf(c1a, c1b), fmaxf(c2a, c2b));
    g_yb[b * 9800 + w]        = fmaxf(y0, 0.f);
    g_yb[b * 9800 + 4900 + w] = fmaxf(y1, 0.f);
}

// ---------------- branch b stage 2 -> cat[:, 2450:] ------------------------------
__global__ void k_b2(const float* __restrict__ w6, const float* __restrict__ b6) {
    __shared__ float sy[2][96];
    __shared__ float sw[128];
    __shared__ float sb2[32];
    int b = blockIdx.x;
    int u0 = blockIdx.y * 8;
    int tid = threadIdx.y * 32 + threadIdx.x;
    int c0 = u0 * 12;
    if (tid < 192) {
        int row = tid / 96, cc = tid % 96;
        sy[row][cc] = g_yb[b * 9800 + row * 4900 + c0 + cc];
    }
    if (tid < 128) sw[tid] = w6[tid];
    if (tid < 32)  sb2[tid] = b6[tid];
    __syncthreads();
    int c = threadIdx.x, ul = threadIdx.y;
    int base = ul * 12;
    float w00 = sw[c*4], w01 = sw[c*4+1], w10 = sw[c*4+2], w11 = sw[c*4+3];
    float best = -1e30f;
#pragma unroll
    for (int r = 0; r < 6; r++) {
        float v = sb2[c] + sy[0][base+2*r]*w00 + sy[0][base+2*r+1]*w01
                         + sy[1][base+2*r]*w10 + sy[1][base+2*r+1]*w11;
        best = fmaxf(best, v);
    }
    g_cat[b * CAT_LDA + 2450 + c * 408 + (u0 + ul)] = fmaxf(best, 0.f);
}

// ---------------- final tiny GEMM -------------------------------------------------
__global__ void k_f3(const float* __restrict__ Wf3, const float* __restrict__ bf3,
                     float* __restrict__ out) {
    int b = blockIdx.x >> 1, n = blockIdx.x & 1;
    int lane = threadIdx.x;
    float s = 0.f;
    for (int k = lane; k < 2000; k += 32) s += g_z2[b * 2000 + k] * Wf3[k * 2 + n];
#pragma unroll
    for (int o = 16; o; o >>= 1) s += __shfl_xor_sync(0xffffffff, s, o);
    if (lane == 0) out[b * 2 + n] = s + bf3[n];
}

// ---------------- launch -----------------------------------------------------------
extern "C" void kernel_launch(void* const* d_in, const int* in_sizes, int n_in,
                              void* d_out, int out_size) {
    const float* x1  = (const float*)d_in[0];
    const float* x2  = (const float*)d_in[1];
    const float* w1  = (const float*)d_in[2];
    const float* b1  = (const float*)d_in[3];
    const float* Wa  = (const float*)d_in[4];
    const float* ba  = (const float*)d_in[5];
    const float* Wb  = (const float*)d_in[6];
    const float* bb  = (const float*)d_in[7];
    const float* Wc  = (const float*)d_in[8];
    const float* bc  = (const float*)d_in[9];
    const float* lw  = (const float*)d_in[10];
    const float* lb  = (const float*)d_in[11];
    const float* w5  = (const float*)d_in[12];
    const float* b5  = (const float*)d_in[13];
    const float* w6  = (const float*)d_in[14];
    const float* b6  = (const float*)d_in[15];
    const float* Wf1 = (const float*)d_in[16];
    const float* bf1 = (const float*)d_in[17];
    const float* Wf2 = (const float*)d_in[18];
    const float* bf2 = (const float*)d_in[19];
    const float* Wf3 = (const float*)d_in[20];
    const float* bf3 = (const float*)d_in[21];
    float* out = (float*)d_out;

    float *A1, *h1, *h2, *cat, *z1, *z2, *part;
    cudaGetSymbolAddress((void**)&A1,  g_A1);
    cudaGetSymbolAddress((void**)&h1,  g_h1);
    cudaGetSymbolAddress((void**)&h2,  g_h2);
    cudaGetSymbolAddress((void**)&cat, g_cat);
    cudaGetSymbolAddress((void**)&z1,  g_z1);
    cudaGetSymbolAddress((void**)&z2,  g_z2);
    cudaGetSymbolAddress((void**)&part, g_part);

    static int smem_set = 0;
    if (!smem_set) {
        cudaFuncSetAttribute(k_mma, cudaFuncAttributeMaxDynamicSharedMemorySize,
                             SMEM_MMA_BYTES);
        smem_set = 1;
    }

    // branch a front (also zeroes A1 pad)
    k_a_front<<<(64 * A1_LDA) / 256, 256>>>(x1, w1, b1);
    // h1 = relu(A1 @ Wa + ba): K=4899, N=1000, kLen=160, S=32
    k_mma<<<dim3(8, 32), 256, SMEM_MMA_BYTES>>>(A1, A1_LDA, Wa, part, 4899, 1000, 160);
    k_reduce<<<(64 * H1_LDA) / 256, 256>>>(ba, h1, 1000, H1_LDA, 32, 1);
    // h2 = relu(h1 @ Wb + bb): K=1000, N=500, kLen=32, S=32
    k_mma<<<dim3(4, 32), 256, SMEM_MMA_BYTES>>>(h1, H1_LDA, Wb, part, 1000, 500, 32);
    k_reduce<<<(64 * 500 + 255) / 256, 256>>>(bb, h2, 500, 500, 32, 1);
    // a3 = h2 @ Wc + bc
    k_gemm3<<<576, 32>>>(Wc, bc);
    // dynamic conv -> cat[:, :2450]
    k_dyn<<<dim3(64, 10), 256>>>(x1, lw, lb);
    // branch b
    k_b1<<<(64 * 4900 + 255) / 256, 256>>>(x2, w5, b5);
    k_b2<<<dim3(64, 51), dim3(32, 8)>>>(w6, b6);
    // zero cat pad columns
    k_zcat<<<(64 * (CAT_LDA - 15506) + 255) / 256, 256>>>();
    // z1 = relu(cat @ Wf1 + bf1): K=15506, N=8000, kLen=3904, S=4
    k_mma<<<dim3(63, 4), 256, SMEM_MMA_BYTES>>>(cat, CAT_LDA, Wf1, part, 15506, 8000, 3904);
    k_reduce<<<(64 * Z1_LDA) / 256, 256>>>(bf1, z1, 8000, Z1_LDA, 4, 1);
    // z2 = relu(z1 @ Wf2 + bf2): K=8000, N=2000, kLen=512, S=16
    k_mma<<<dim3(16, 16), 256, SMEM_MMA_BYTES>>>(z1, Z1_LDA, Wf2, part, 8000, 2000, 512);
    k_reduce<<<(64 * 2000 + 255) / 256, 256>>>(bf2, z2, 2000, 2000, 16, 1);
    // out = z2 @ Wf3 + bf3
    k_f3<<<128, 32>>>(Wf3, bf3, out);
}